// round 2
// baseline (speedup 1.0000x reference)
#include <cuda_runtime.h>
#include <math.h>

#define NN 325
#define BB 64
#define HH 64

// ---------------- device scratch (static allocations; no cudaMalloc) --------
__device__ float g_S[2 * NN * NN];      // S1, S2 row-major
__device__ float g_rs[NN];
__device__ float g_cs[NN];
__device__ float g_xx[NN * BB];             // layer0 x part, [n][1][b]
__device__ float g_xxcheb[4 * NN * BB];     // layer0 x-part cheb mats (slots m-1)
__device__ float g_x1cheb[4 * NN * HH * BB];// layer1 x-part cheb mats
__device__ float g_hcheb[4 * NN * HH * BB]; // h-part cheb mats (reused)
__device__ float g_h0a[NN * HH * BB];
__device__ float g_h0b[NN * HH * BB];
__device__ float g_h1a[NN * HH * BB];
__device__ float g_h1b[NN * HH * BB];
__device__ float g_u[NN * HH * BB];
__device__ float g_rh[NN * HH * BB];

// ---------------- support construction --------------------------------------
__global__ void sums_kernel(const float* __restrict__ adj, float* __restrict__ rs,
                            float* __restrict__ cs) {
    int n = blockIdx.x * blockDim.x + threadIdx.x;
    if (n < NN) {
        float r = 0.f, c = 0.f;
        for (int j = 0; j < NN; j++) {
            r += adj[(long)n * NN + j];
            c += adj[(long)j * NN + n];
        }
        rs[n] = r;
        cs[n] = c;
    }
}

__global__ void build_S_kernel(const float* __restrict__ adj, const float* __restrict__ rs,
                               const float* __restrict__ cs, float* __restrict__ S) {
    int i = blockIdx.x * blockDim.x + threadIdx.x;
    if (i < NN * NN) {
        int r = i / NN, c = i % NN;
        // S1[r][c] = adj[c][r] / rowsum[c];  S2[r][c] = adj[r][c] / colsum[c]
        S[i] = adj[(long)c * NN + r] / rs[c];
        S[NN * NN + i] = adj[i] / cs[c];
    }
}

// ---------------- packing ----------------------------------------------------
// init_state [B][N*HH] -> h [n][c][b]
__global__ void pack_state_kernel(const float* __restrict__ st, float* __restrict__ h) {
    int i = blockIdx.x * blockDim.x + threadIdx.x;
    if (i < NN * HH * BB) {
        int b = i % BB;
        int nc = i / BB;
        h[i] = st[(long)b * NN * HH + nc];
    }
}

// inputs slice [B][N] -> xx [n][b]
__global__ void pack_x_kernel(const float* __restrict__ inp, float* __restrict__ xx) {
    int i = blockIdx.x * blockDim.x + threadIdx.x;
    if (i < NN * BB) {
        int n = i / BB, b = i % BB;
        xx[i] = inp[(long)b * NN + n];
    }
}

__global__ void zero_kernel(float* __restrict__ y, int n) {
    int i = blockIdx.x * blockDim.x + threadIdx.x;
    if (i < n) y[i] = 0.f;
}

// ---------------- SpMM: Y[z] = alpha * S[z] @ X[z] + beta * Z[z] ------------
// S: [2][NN][NN], X/Z/Y: [NN][J]; per-z strides allow shared or distinct bufs.
__global__ void __launch_bounds__(128) smm_kernel(
    const float* __restrict__ Sbase,
    const float* __restrict__ X, long xz,
    const float* __restrict__ Z, long zz,
    float* __restrict__ Y, long yz,
    int J, float alpha, float beta) {
    const int z = blockIdx.z;
    const float* S = Sbase + (long)z * NN * NN;
    const float* Xp = X + (long)z * xz;
    const float* Zp = Z ? (Z + (long)z * zz) : (const float*)0;
    float* Yp = Y + (long)z * yz;

    __shared__ float Ssub[64][17];
    __shared__ float Xsub[16][128];

    const int tid = threadIdx.x;
    const int n0 = blockIdx.y * 64;
    const int j0 = blockIdx.x * 128;
    const int tc = tid & 15;   // col group (8 cols)
    const int tr = tid >> 4;   // row group (8 rows)

    float acc[8][8];
#pragma unroll
    for (int i = 0; i < 8; i++)
#pragma unroll
        for (int j = 0; j < 8; j++) acc[i][j] = 0.f;

    const int li = tid >> 4;        // S-load row base
    const int lkk = tid & 15;       // S-load k
    const int xkk = tid >> 5;       // X-load k base
    const int xj = (tid & 31) * 4;  // X-load col

    for (int k0 = 0; k0 < NN; k0 += 16) {
#pragma unroll
        for (int ph = 0; ph < 8; ph++) {
            int i = li + ph * 8;
            int n = n0 + i;
            int k = k0 + lkk;
            Ssub[i][lkk] = (n < NN && k < NN) ? S[(long)n * NN + k] : 0.f;
        }
#pragma unroll
        for (int ph = 0; ph < 4; ph++) {
            int kk = xkk + ph * 4;
            int k = k0 + kk;
            int j = j0 + xj;
            float4 v = make_float4(0.f, 0.f, 0.f, 0.f);
            if (k < NN && j < J)
                v = *reinterpret_cast<const float4*>(&Xp[(long)k * J + j]);
            *reinterpret_cast<float4*>(&Xsub[kk][xj]) = v;
        }
        __syncthreads();
#pragma unroll
        for (int kk = 0; kk < 16; kk++) {
            float a[8], b[8];
#pragma unroll
            for (int i = 0; i < 8; i++) a[i] = Ssub[tr * 8 + i][kk];
            float4 b0 = *reinterpret_cast<const float4*>(&Xsub[kk][tc * 8]);
            float4 b1 = *reinterpret_cast<const float4*>(&Xsub[kk][tc * 8 + 4]);
            b[0] = b0.x; b[1] = b0.y; b[2] = b0.z; b[3] = b0.w;
            b[4] = b1.x; b[5] = b1.y; b[6] = b1.z; b[7] = b1.w;
#pragma unroll
            for (int i = 0; i < 8; i++)
#pragma unroll
                for (int j = 0; j < 8; j++) acc[i][j] += a[i] * b[j];
        }
        __syncthreads();
    }

#pragma unroll
    for (int i = 0; i < 8; i++) {
        int n = n0 + tr * 8 + i;
        if (n < NN) {
#pragma unroll
            for (int j = 0; j < 8; j++) {
                int jj = j0 + tc * 8 + j;
                if (jj < J) {
                    float v = alpha * acc[i][j];
                    if (Zp) v += beta * Zp[(long)n * J + jj];
                    Yp[(long)n * J + jj] = v;
                }
            }
        }
    }
}

// ---------------- dense xs@W with fused activation ---------------------------
// One block per node n. out[b][o] = sum_k A[b][k] * W[k][o],
// k = c_global*5 + m, c_global < Cx -> x part, else h part (Ch=HH).
// mode 0: gate -> sigmoid; r part fused to rh_out = sigmoid(.)*h_old; u stored.
// mode 1: candidate -> c=tanh(.), h_new = u*h_old + (1-u)*c
__global__ void __launch_bounds__(128) dense_kernel(
    const float* __restrict__ x0x, const float* __restrict__ xcheb, int Cx,
    const float* __restrict__ h0, const float* __restrict__ hcheb,
    const float* __restrict__ W, const float* __restrict__ bias, int O, int K,
    int mode,
    float* __restrict__ rh_out, float* __restrict__ u_out,
    const float* __restrict__ u_in, const float* __restrict__ h_old,
    float* __restrict__ h_new) {
    const int n = blockIdx.x;
    const int tid = threadIdx.x;
    const int tc = tid & 15;
    const int tr = tid >> 4;

    __shared__ float Ash[8][64];
    __shared__ float Wsh[8][128];

    float acc[8][8];
#pragma unroll
    for (int i = 0; i < 8; i++)
#pragma unroll
        for (int j = 0; j < 8; j++) acc[i][j] = 0.f;

    const int akk = tid >> 4;         // 0..7
    const int ab4 = (tid & 15) * 4;   // 0..60

    for (int k0 = 0; k0 < K; k0 += 8) {
        // A tile: rows are feature k, cols are batch b
        {
            int k = k0 + akk;
            float4 v = make_float4(0.f, 0.f, 0.f, 0.f);
            if (k < K) {
                int c = k / 5, m = k % 5;
                const float* p;
                if (c < Cx) {
                    p = (m == 0) ? (x0x + ((long)n * Cx + c) * BB)
                                 : (xcheb + (((long)(m - 1) * NN + n) * Cx + c) * BB);
                } else {
                    int ch = c - Cx;
                    p = (m == 0) ? (h0 + ((long)n * HH + ch) * BB)
                                 : (hcheb + (((long)(m - 1) * NN + n) * HH + ch) * BB);
                }
                v = *reinterpret_cast<const float4*>(&p[ab4]);
            }
            *reinterpret_cast<float4*>(&Ash[akk][ab4]) = v;
        }
        // W tile: flat conflict-free loads
        {
            int flat = tid * 4;  // 0..508
#pragma unroll
            for (int ph = 0; ph < 2; ph++) {
                int f = flat + ph * 512;
                int kk = f >> 7;
                int o = f & 127;
                int k = k0 + kk;
                float4 v = make_float4(0.f, 0.f, 0.f, 0.f);
                if (k < K && o < O)
                    v = *reinterpret_cast<const float4*>(&W[(long)k * O + o]);
                *reinterpret_cast<float4*>(&Wsh[kk][o]) = v;
            }
        }
        __syncthreads();
#pragma unroll
        for (int kk = 0; kk < 8; kk++) {
            float4 a0 = *reinterpret_cast<const float4*>(&Ash[kk][tr * 8]);
            float4 a1 = *reinterpret_cast<const float4*>(&Ash[kk][tr * 8 + 4]);
            float4 w0 = *reinterpret_cast<const float4*>(&Wsh[kk][tc * 8]);
            float4 w1 = *reinterpret_cast<const float4*>(&Wsh[kk][tc * 8 + 4]);
            float a[8] = {a0.x, a0.y, a0.z, a0.w, a1.x, a1.y, a1.z, a1.w};
            float w[8] = {w0.x, w0.y, w0.z, w0.w, w1.x, w1.y, w1.z, w1.w};
#pragma unroll
            for (int i = 0; i < 8; i++)
#pragma unroll
                for (int j = 0; j < 8; j++) acc[i][j] += a[i] * w[j];
        }
        __syncthreads();
    }

    // epilogue
    if (mode == 0) {
#pragma unroll
        for (int j = 0; j < 8; j++) {
            int o = tc * 8 + j;
            if (o < O) {
                float bo = bias[o];
                float s[8];
#pragma unroll
                for (int i = 0; i < 8; i++)
                    s[i] = 1.f / (1.f + expf(-(acc[i][j] + bo)));
                if (o < HH) {
                    // r: fuse rh = r * h_old
                    long base = ((long)n * HH + o) * BB + tr * 8;
                    float4 hh0 = *reinterpret_cast<const float4*>(&h_old[base]);
                    float4 hh1 = *reinterpret_cast<const float4*>(&h_old[base + 4]);
                    float4 v0 = make_float4(s[0] * hh0.x, s[1] * hh0.y, s[2] * hh0.z, s[3] * hh0.w);
                    float4 v1 = make_float4(s[4] * hh1.x, s[5] * hh1.y, s[6] * hh1.z, s[7] * hh1.w);
                    *reinterpret_cast<float4*>(&rh_out[base]) = v0;
                    *reinterpret_cast<float4*>(&rh_out[base + 4]) = v1;
                } else {
                    long base = ((long)n * HH + (o - HH)) * BB + tr * 8;
                    float4 v0 = make_float4(s[0], s[1], s[2], s[3]);
                    float4 v1 = make_float4(s[4], s[5], s[6], s[7]);
                    *reinterpret_cast<float4*>(&u_out[base]) = v0;
                    *reinterpret_cast<float4*>(&u_out[base + 4]) = v1;
                }
            }
        }
    } else {
#pragma unroll
        for (int j = 0; j < 8; j++) {
            int o = tc * 8 + j;
            if (o < O) {
                float bo = bias[o];
                long base = ((long)n * HH + o) * BB + tr * 8;
                float4 uu0 = *reinterpret_cast<const float4*>(&u_in[base]);
                float4 uu1 = *reinterpret_cast<const float4*>(&u_in[base + 4]);
                float4 hh0 = *reinterpret_cast<const float4*>(&h_old[base]);
                float4 hh1 = *reinterpret_cast<const float4*>(&h_old[base + 4]);
                float4 v0, v1;
                float c0 = tanhf(acc[0][j] + bo), c1 = tanhf(acc[1][j] + bo);
                float c2 = tanhf(acc[2][j] + bo), c3 = tanhf(acc[3][j] + bo);
                float c4 = tanhf(acc[4][j] + bo), c5 = tanhf(acc[5][j] + bo);
                float c6 = tanhf(acc[6][j] + bo), c7 = tanhf(acc[7][j] + bo);
                v0.x = uu0.x * hh0.x + (1.f - uu0.x) * c0;
                v0.y = uu0.y * hh0.y + (1.f - uu0.y) * c1;
                v0.z = uu0.z * hh0.z + (1.f - uu0.z) * c2;
                v0.w = uu0.w * hh0.w + (1.f - uu0.w) * c3;
                v1.x = uu1.x * hh1.x + (1.f - uu1.x) * c4;
                v1.y = uu1.y * hh1.y + (1.f - uu1.y) * c5;
                v1.z = uu1.z * hh1.z + (1.f - uu1.z) * c6;
                v1.w = uu1.w * hh1.w + (1.f - uu1.w) * c7;
                *reinterpret_cast<float4*>(&h_new[base]) = v0;
                *reinterpret_cast<float4*>(&h_new[base + 4]) = v1;
            }
        }
    }
}

// ---------------- final projection -------------------------------------------
// out[b][n] = sum_c h1[n][c][b] * Wfc[c] + bfc
__global__ void out_kernel(const float* __restrict__ h1, const float* __restrict__ Wfc,
                           const float* __restrict__ bfc, float* __restrict__ out) {
    int n = blockIdx.x;
    int b = threadIdx.x;
    float s = bfc[0];
    const float* hp = h1 + (long)n * HH * BB + b;
#pragma unroll
    for (int c = 0; c < HH; c++) s += hp[c * BB] * Wfc[c];
    out[(long)b * NN + n] = s;
}

// ---------------- host orchestration -----------------------------------------
static inline void smm_launch(const float* S, const float* X, long xz,
                              const float* Z, long zz, float* Y, long yz,
                              int J, float alpha, float beta) {
    dim3 grid((J + 127) / 128, (NN + 63) / 64, 2);
    smm_kernel<<<grid, 128>>>(S, X, xz, Z, zz, Y, yz, J, alpha, beta);
}

extern "C" void kernel_launch(void* const* d_in, const int* in_sizes, int n_in,
                              void* d_out, int out_size) {
    const float* inputs = (const float*)d_in[0];
    const float* init_state = (const float*)d_in[1];
    const float* adj = (const float*)d_in[2];
    const float* Wg0 = (const float*)d_in[3];
    const float* bg0 = (const float*)d_in[4];
    const float* Wc0 = (const float*)d_in[5];
    const float* bc0 = (const float*)d_in[6];
    const float* Wg1 = (const float*)d_in[7];
    const float* bg1 = (const float*)d_in[8];
    const float* Wc1 = (const float*)d_in[9];
    const float* bc1 = (const float*)d_in[10];
    const float* Wfc = (const float*)d_in[11];
    const float* bfc = (const float*)d_in[12];
    float* out = (float*)d_out;

    void* p;
    cudaGetSymbolAddress(&p, g_S);      float* S = (float*)p;
    cudaGetSymbolAddress(&p, g_rs);     float* rs = (float*)p;
    cudaGetSymbolAddress(&p, g_cs);     float* cs = (float*)p;
    cudaGetSymbolAddress(&p, g_xx);     float* xx = (float*)p;
    cudaGetSymbolAddress(&p, g_xxcheb); float* xxcheb = (float*)p;
    cudaGetSymbolAddress(&p, g_x1cheb); float* x1cheb = (float*)p;
    cudaGetSymbolAddress(&p, g_hcheb);  float* hcheb = (float*)p;
    cudaGetSymbolAddress(&p, g_h0a);    float* h0a = (float*)p;
    cudaGetSymbolAddress(&p, g_h0b);    float* h0b = (float*)p;
    cudaGetSymbolAddress(&p, g_h1a);    float* h1a = (float*)p;
    cudaGetSymbolAddress(&p, g_h1b);    float* h1b = (float*)p;
    cudaGetSymbolAddress(&p, g_u);      float* u = (float*)p;
    cudaGetSymbolAddress(&p, g_rh);     float* rh = (float*)p;

    const long hs = (long)NN * HH * BB;       // h-part mat slot size
    const long xs0 = (long)NN * BB;           // layer0 x-part slot size
    const int nelem = NN * HH * BB;

    // supports
    sums_kernel<<<(NN + 255) / 256, 256>>>(adj, rs, cs);
    build_S_kernel<<<(NN * NN + 255) / 256, 256>>>(adj, rs, cs, S);

    // pack initial states
    pack_state_kernel<<<(nelem + 255) / 256, 256>>>(init_state, h0a);
    pack_state_kernel<<<(nelem + 255) / 256, 256>>>(init_state + (long)BB * NN * HH, h1a);

    // zero output row 0
    zero_kernel<<<(BB * NN + 255) / 256, 256>>>(out, BB * NN);

    for (int t = 0; t < 12; t++) {
        float* h0_old = (t & 1) ? h0b : h0a;
        float* h0_new = (t & 1) ? h0a : h0b;
        float* h1_old = (t & 1) ? h1b : h1a;
        float* h1_new = (t & 1) ? h1a : h1b;

        // ---- layer 0 ----
        pack_x_kernel<<<(NN * BB + 255) / 256, 256>>>(inputs + (long)t * BB * NN, xx);

        // x-part cheb (Cx=1, J=64), shared by gate+candidate
        smm_launch(S, xx, 0, 0, 0, xxcheb, 2 * xs0, BB, 1.f, 0.f);
        smm_launch(S, xxcheb, 2 * xs0, xx, 0, xxcheb + xs0, 2 * xs0, BB, 2.f, -1.f);

        // gate: h-part cheb on h0_old (J=4096)
        smm_launch(S, h0_old, 0, 0, 0, hcheb, 2 * hs, HH * BB, 1.f, 0.f);
        smm_launch(S, hcheb, 2 * hs, h0_old, 0, hcheb + hs, 2 * hs, HH * BB, 2.f, -1.f);
        dense_kernel<<<NN, 128>>>(xx, xxcheb, 1, h0_old, hcheb, Wg0, bg0, 2 * HH, 325, 0,
                                  rh, u, 0, h0_old, 0);

        // candidate: h-part cheb on r*h
        smm_launch(S, rh, 0, 0, 0, hcheb, 2 * hs, HH * BB, 1.f, 0.f);
        smm_launch(S, hcheb, 2 * hs, rh, 0, hcheb + hs, 2 * hs, HH * BB, 2.f, -1.f);
        dense_kernel<<<NN, 128>>>(xx, xxcheb, 1, rh, hcheb, Wc0, bc0, HH, 325, 1,
                                  0, 0, u, h0_old, h0_new);

        // ---- layer 1 (x part = h0_new) ----
        smm_launch(S, h0_new, 0, 0, 0, x1cheb, 2 * hs, HH * BB, 1.f, 0.f);
        smm_launch(S, x1cheb, 2 * hs, h0_new, 0, x1cheb + hs, 2 * hs, HH * BB, 2.f, -1.f);

        smm_launch(S, h1_old, 0, 0, 0, hcheb, 2 * hs, HH * BB, 1.f, 0.f);
        smm_launch(S, hcheb, 2 * hs, h1_old, 0, hcheb + hs, 2 * hs, HH * BB, 2.f, -1.f);
        dense_kernel<<<NN, 128>>>(h0_new, x1cheb, HH, h1_old, hcheb, Wg1, bg1, 2 * HH, 640, 0,
                                  rh, u, 0, h1_old, 0);

        smm_launch(S, rh, 0, 0, 0, hcheb, 2 * hs, HH * BB, 1.f, 0.f);
        smm_launch(S, hcheb, 2 * hs, rh, 0, hcheb + hs, 2 * hs, HH * BB, 2.f, -1.f);
        dense_kernel<<<NN, 128>>>(h0_new, x1cheb, HH, rh, hcheb, Wc1, bc1, HH, 640, 1,
                                  0, 0, u, h1_old, h1_new);

        out_kernel<<<NN, BB>>>(h1_new, Wfc, bfc, out + (long)(t + 1) * BB * NN);
    }
}

// round 3
// speedup vs baseline: 1.1581x; 1.1581x over previous
#include <cuda_runtime.h>
#include <math.h>

#define NN 325
#define BB 64
#define HH 64
#define KT 16

// ---------------- device scratch --------------------------------------------
__device__ float g_S[2 * NN * NN];
__device__ float g_rs[NN];
__device__ float g_cs[NN];
__device__ float g_xx[NN * BB];
__device__ float g_xxcheb[4 * NN * BB];
__device__ float g_x1cheb[4 * NN * HH * BB];
__device__ float g_hcheb[4 * NN * HH * BB];
__device__ float g_h0a[NN * HH * BB];
__device__ float g_h0b[NN * HH * BB];
__device__ float g_h1a[NN * HH * BB];
__device__ float g_h1b[NN * HH * BB];
__device__ float g_u[NN * HH * BB];
__device__ float g_rh[NN * HH * BB];

// ---------------- support construction --------------------------------------
__global__ void sums_kernel(const float* __restrict__ adj, float* __restrict__ rs,
                            float* __restrict__ cs) {
    int n = blockIdx.x * blockDim.x + threadIdx.x;
    if (n < NN) {
        float r = 0.f, c = 0.f;
        for (int j = 0; j < NN; j++) {
            r += adj[(long)n * NN + j];
            c += adj[(long)j * NN + n];
        }
        rs[n] = r;
        cs[n] = c;
    }
}

__global__ void build_S_kernel(const float* __restrict__ adj, const float* __restrict__ rs,
                               const float* __restrict__ cs, float* __restrict__ S) {
    int i = blockIdx.x * blockDim.x + threadIdx.x;
    if (i < NN * NN) {
        int r = i / NN, c = i % NN;
        S[i] = adj[(long)c * NN + r] / rs[c];
        S[NN * NN + i] = adj[i] / cs[c];
    }
}

// ---------------- packing ----------------------------------------------------
__global__ void pack_state_kernel(const float* __restrict__ st, float* __restrict__ h) {
    int i = blockIdx.x * blockDim.x + threadIdx.x;
    if (i < NN * HH * BB) {
        int b = i % BB;
        int nc = i / BB;
        h[i] = st[(long)b * NN * HH + nc];
    }
}

__global__ void pack_x_kernel(const float* __restrict__ inp, float* __restrict__ xx) {
    int i = blockIdx.x * blockDim.x + threadIdx.x;
    if (i < NN * BB) {
        int n = i / BB, b = i % BB;
        xx[i] = inp[(long)b * NN + n];
    }
}

__global__ void zero_kernel(float* __restrict__ y, int n) {
    int i = blockIdx.x * blockDim.x + threadIdx.x;
    if (i < n) y[i] = 0.f;
}

// ---------------- pipelined SpMM ---------------------------------------------
// Per z: support = z&1 (selects S1/S2), input-set = z>>1 (selects X0/X1 ...).
// Y(z) = alpha * S_{z&1} @ (Xsel + (z&1)*xz)  + beta * (Zsel + (z&1)*zz)
// written to (Ysel + (z&1)*yz). 64(n) x 128(j) tile, K-tile 16, double-buffered.
__global__ void __launch_bounds__(128) smm_kernel(
    const float* __restrict__ Sbase,
    const float* __restrict__ X0, const float* __restrict__ X1, long xz,
    const float* __restrict__ Z0, const float* __restrict__ Z1, long zz,
    float* __restrict__ Y0, float* __restrict__ Y1, long yz,
    int J, float alpha, float beta) {
    const int z = blockIdx.z;
    const float* S = Sbase + (long)(z & 1) * NN * NN;
    const float* Xp = ((z >> 1) ? X1 : X0) + (long)(z & 1) * xz;
    const float* Zsel = (z >> 1) ? Z1 : Z0;
    const float* Zp = Zsel ? (Zsel + (long)(z & 1) * zz) : (const float*)0;
    float* Yp = ((z >> 1) ? Y1 : Y0) + (long)(z & 1) * yz;

    __shared__ float Ssub[2][KT][68];   // transposed: [kk][row], pad 68 for banks+align
    __shared__ float Xsub[2][KT][128];

    const int tid = threadIdx.x;
    const int n0 = blockIdx.y * 64;
    const int j0 = blockIdx.x * 128;
    const int tc = tid & 15;
    const int tr = tid >> 4;

    const int li = tid >> 4;        // S rows li + 8*ph
    const int lkk = tid & 15;       // S k within tile
    const int xkk = tid >> 5;       // X rows xkk + 4*ph
    const int xj = (tid & 31) * 4;  // X col

    float acc[8][8];
#pragma unroll
    for (int i = 0; i < 8; i++)
#pragma unroll
        for (int j = 0; j < 8; j++) acc[i][j] = 0.f;

    float sReg[8];
    float4 xReg[4];
    const bool xjok = (j0 + xj) < J;

    // ---- prefetch tile 0 ----
    {
        int k = lkk;
        bool kok = k < NN;
#pragma unroll
        for (int ph = 0; ph < 8; ph++) {
            int n = n0 + li + ph * 8;
            sReg[ph] = (kok && n < NN) ? S[(long)n * NN + k] : 0.f;
        }
#pragma unroll
        for (int ph = 0; ph < 4; ph++) {
            int kx = xkk + ph * 4;
            float4 v = make_float4(0.f, 0.f, 0.f, 0.f);
            if (kx < NN && xjok) v = *reinterpret_cast<const float4*>(&Xp[(long)kx * J + j0 + xj]);
            xReg[ph] = v;
        }
#pragma unroll
        for (int ph = 0; ph < 8; ph++) Ssub[0][lkk][li + ph * 8] = sReg[ph];
#pragma unroll
        for (int ph = 0; ph < 4; ph++)
            *reinterpret_cast<float4*>(&Xsub[0][xkk + ph * 4][xj]) = xReg[ph];
    }
    __syncthreads();

    const int T = (NN + KT - 1) / KT;  // 21
    for (int t = 0; t < T; t++) {
        const int buf = t & 1;
        const int k0n = (t + 1) * KT;
        if (t + 1 < T) {
            int k = k0n + lkk;
            bool kok = k < NN;
#pragma unroll
            for (int ph = 0; ph < 8; ph++) {
                int n = n0 + li + ph * 8;
                sReg[ph] = (kok && n < NN) ? S[(long)n * NN + k] : 0.f;
            }
#pragma unroll
            for (int ph = 0; ph < 4; ph++) {
                int kx = k0n + xkk + ph * 4;
                float4 v = make_float4(0.f, 0.f, 0.f, 0.f);
                if (kx < NN && xjok)
                    v = *reinterpret_cast<const float4*>(&Xp[(long)kx * J + j0 + xj]);
                xReg[ph] = v;
            }
        }
#pragma unroll
        for (int kk = 0; kk < KT; kk++) {
            float4 a0 = *reinterpret_cast<const float4*>(&Ssub[buf][kk][tr * 8]);
            float4 a1 = *reinterpret_cast<const float4*>(&Ssub[buf][kk][tr * 8 + 4]);
            float4 b0 = *reinterpret_cast<const float4*>(&Xsub[buf][kk][tc * 8]);
            float4 b1 = *reinterpret_cast<const float4*>(&Xsub[buf][kk][tc * 8 + 4]);
            float a[8] = {a0.x, a0.y, a0.z, a0.w, a1.x, a1.y, a1.z, a1.w};
            float b[8] = {b0.x, b0.y, b0.z, b0.w, b1.x, b1.y, b1.z, b1.w};
#pragma unroll
            for (int i = 0; i < 8; i++)
#pragma unroll
                for (int j = 0; j < 8; j++) acc[i][j] += a[i] * b[j];
        }
        __syncthreads();
        if (t + 1 < T) {
            const int nb = buf ^ 1;
#pragma unroll
            for (int ph = 0; ph < 8; ph++) Ssub[nb][lkk][li + ph * 8] = sReg[ph];
#pragma unroll
            for (int ph = 0; ph < 4; ph++)
                *reinterpret_cast<float4*>(&Xsub[nb][xkk + ph * 4][xj]) = xReg[ph];
            __syncthreads();
        }
    }

#pragma unroll
    for (int i = 0; i < 8; i++) {
        int n = n0 + tr * 8 + i;
        if (n < NN) {
            int jj = j0 + tc * 8;
            if (jj < J) {
                float4 v0, v1;
                v0.x = alpha * acc[i][0]; v0.y = alpha * acc[i][1];
                v0.z = alpha * acc[i][2]; v0.w = alpha * acc[i][3];
                v1.x = alpha * acc[i][4]; v1.y = alpha * acc[i][5];
                v1.z = alpha * acc[i][6]; v1.w = alpha * acc[i][7];
                if (Zp) {
                    float4 z0 = *reinterpret_cast<const float4*>(&Zp[(long)n * J + jj]);
                    float4 z1 = *reinterpret_cast<const float4*>(&Zp[(long)n * J + jj + 4]);
                    v0.x += beta * z0.x; v0.y += beta * z0.y;
                    v0.z += beta * z0.z; v0.w += beta * z0.w;
                    v1.x += beta * z1.x; v1.y += beta * z1.y;
                    v1.z += beta * z1.z; v1.w += beta * z1.w;
                }
                *reinterpret_cast<float4*>(&Yp[(long)n * J + jj]) = v0;
                *reinterpret_cast<float4*>(&Yp[(long)n * J + jj + 4]) = v1;
            }
        }
    }
}

// ---------------- pipelined dense xs@W with fused activation -----------------
// One block per node n, K-tile 16, double buffered.
// mode 0: gate -> sigmoid; r fused to rh_out = sig*h_old; u stored.
// mode 1: candidate -> h_new = u*h_old + (1-u)*tanh(.); optional fused output
//         projection out[b][n] = sum_c h_new[c][b]*Wfc[c] + bfc.
__global__ void __launch_bounds__(128) dense_kernel(
    const float* __restrict__ x0x, const float* __restrict__ xcheb, int Cx,
    const float* __restrict__ h0, const float* __restrict__ hcheb,
    const float* __restrict__ W, const float* __restrict__ bias, int O, int K,
    int mode,
    float* __restrict__ rh_out, float* __restrict__ u_out,
    const float* __restrict__ u_in, const float* __restrict__ h_old,
    float* __restrict__ h_new,
    const float* __restrict__ Wfc, const float* __restrict__ bfc,
    float* __restrict__ outp) {
    const int n = blockIdx.x;
    const int tid = threadIdx.x;
    const int tc = tid & 15;
    const int tr = tid >> 4;

    __shared__ float Ash[2][KT][64];
    __shared__ float Wsh[2][KT][128];
    __shared__ float red[16][64];

    float acc[8][8];
#pragma unroll
    for (int i = 0; i < 8; i++)
#pragma unroll
        for (int j = 0; j < 8; j++) acc[i][j] = 0.f;

    const int akk = tid >> 3;        // 0..15 (A row, W row)
    const int ab = (tid & 7) * 8;    // A col base (2 float4)
    const int ob = (tid & 7) * 16;   // W col base (4 float4)

    float4 aR[2], wR[4];

    // prefetch helper logic inline, tile index via k0
    {
        int k = akk;
        aR[0] = make_float4(0.f, 0.f, 0.f, 0.f);
        aR[1] = make_float4(0.f, 0.f, 0.f, 0.f);
        if (k < K) {
            int c = k / 5, m = k % 5;
            const float* p;
            if (c < Cx) {
                p = (m == 0) ? (x0x + ((long)n * Cx + c) * BB)
                             : (xcheb + (((long)(m - 1) * NN + n) * Cx + c) * BB);
            } else {
                int ch = c - Cx;
                p = (m == 0) ? (h0 + ((long)n * HH + ch) * BB)
                             : (hcheb + (((long)(m - 1) * NN + n) * HH + ch) * BB);
            }
            aR[0] = *reinterpret_cast<const float4*>(&p[ab]);
            aR[1] = *reinterpret_cast<const float4*>(&p[ab + 4]);
        }
#pragma unroll
        for (int q = 0; q < 4; q++) {
            wR[q] = make_float4(0.f, 0.f, 0.f, 0.f);
            if (k < K && ob < O)
                wR[q] = *reinterpret_cast<const float4*>(&W[(long)k * O + ob + q * 4]);
        }
        *reinterpret_cast<float4*>(&Ash[0][akk][ab]) = aR[0];
        *reinterpret_cast<float4*>(&Ash[0][akk][ab + 4]) = aR[1];
#pragma unroll
        for (int q = 0; q < 4; q++)
            *reinterpret_cast<float4*>(&Wsh[0][akk][ob + q * 4]) = wR[q];
    }
    __syncthreads();

    const int T = (K + KT - 1) / KT;
    for (int t = 0; t < T; t++) {
        const int buf = t & 1;
        const int k0n = (t + 1) * KT;
        if (t + 1 < T) {
            int k = k0n + akk;
            aR[0] = make_float4(0.f, 0.f, 0.f, 0.f);
            aR[1] = make_float4(0.f, 0.f, 0.f, 0.f);
            if (k < K) {
                int c = k / 5, m = k % 5;
                const float* p;
                if (c < Cx) {
                    p = (m == 0) ? (x0x + ((long)n * Cx + c) * BB)
                                 : (xcheb + (((long)(m - 1) * NN + n) * Cx + c) * BB);
                } else {
                    int ch = c - Cx;
                    p = (m == 0) ? (h0 + ((long)n * HH + ch) * BB)
                                 : (hcheb + (((long)(m - 1) * NN + n) * HH + ch) * BB);
                }
                aR[0] = *reinterpret_cast<const float4*>(&p[ab]);
                aR[1] = *reinterpret_cast<const float4*>(&p[ab + 4]);
            }
#pragma unroll
            for (int q = 0; q < 4; q++) {
                wR[q] = make_float4(0.f, 0.f, 0.f, 0.f);
                if (k < K && ob < O)
                    wR[q] = *reinterpret_cast<const float4*>(&W[(long)k * O + ob + q * 4]);
            }
        }
#pragma unroll
        for (int kk = 0; kk < KT; kk++) {
            float4 a0 = *reinterpret_cast<const float4*>(&Ash[buf][kk][tr * 8]);
            float4 a1 = *reinterpret_cast<const float4*>(&Ash[buf][kk][tr * 8 + 4]);
            float4 w0 = *reinterpret_cast<const float4*>(&Wsh[buf][kk][tc * 8]);
            float4 w1 = *reinterpret_cast<const float4*>(&Wsh[buf][kk][tc * 8 + 4]);
            float a[8] = {a0.x, a0.y, a0.z, a0.w, a1.x, a1.y, a1.z, a1.w};
            float w[8] = {w0.x, w0.y, w0.z, w0.w, w1.x, w1.y, w1.z, w1.w};
#pragma unroll
            for (int i = 0; i < 8; i++)
#pragma unroll
                for (int j = 0; j < 8; j++) acc[i][j] += a[i] * w[j];
        }
        __syncthreads();
        if (t + 1 < T) {
            const int nb = buf ^ 1;
            *reinterpret_cast<float4*>(&Ash[nb][akk][ab]) = aR[0];
            *reinterpret_cast<float4*>(&Ash[nb][akk][ab + 4]) = aR[1];
#pragma unroll
            for (int q = 0; q < 4; q++)
                *reinterpret_cast<float4*>(&Wsh[nb][akk][ob + q * 4]) = wR[q];
            __syncthreads();
        }
    }

    // epilogue
    if (mode == 0) {
#pragma unroll
        for (int j = 0; j < 8; j++) {
            int o = tc * 8 + j;
            if (o < O) {
                float bo = bias[o];
                float s[8];
#pragma unroll
                for (int i = 0; i < 8; i++)
                    s[i] = 1.f / (1.f + expf(-(acc[i][j] + bo)));
                if (o < HH) {
                    long base = ((long)n * HH + o) * BB + tr * 8;
                    float4 hh0 = *reinterpret_cast<const float4*>(&h_old[base]);
                    float4 hh1 = *reinterpret_cast<const float4*>(&h_old[base + 4]);
                    float4 v0 = make_float4(s[0] * hh0.x, s[1] * hh0.y, s[2] * hh0.z, s[3] * hh0.w);
                    float4 v1 = make_float4(s[4] * hh1.x, s[5] * hh1.y, s[6] * hh1.z, s[7] * hh1.w);
                    *reinterpret_cast<float4*>(&rh_out[base]) = v0;
                    *reinterpret_cast<float4*>(&rh_out[base + 4]) = v1;
                } else {
                    long base = ((long)n * HH + (o - HH)) * BB + tr * 8;
                    *reinterpret_cast<float4*>(&u_out[base]) = make_float4(s[0], s[1], s[2], s[3]);
                    *reinterpret_cast<float4*>(&u_out[base + 4]) = make_float4(s[4], s[5], s[6], s[7]);
                }
            }
        }
    } else {
        float outacc[8];
#pragma unroll
        for (int i = 0; i < 8; i++) outacc[i] = 0.f;
#pragma unroll
        for (int j = 0; j < 8; j++) {
            int o = tc * 8 + j;
            if (o < O) {
                float bo = bias[o];
                long base = ((long)n * HH + o) * BB + tr * 8;
                float4 uu0 = *reinterpret_cast<const float4*>(&u_in[base]);
                float4 uu1 = *reinterpret_cast<const float4*>(&u_in[base + 4]);
                float4 hh0 = *reinterpret_cast<const float4*>(&h_old[base]);
                float4 hh1 = *reinterpret_cast<const float4*>(&h_old[base + 4]);
                float c0 = tanhf(acc[0][j] + bo), c1 = tanhf(acc[1][j] + bo);
                float c2 = tanhf(acc[2][j] + bo), c3 = tanhf(acc[3][j] + bo);
                float c4 = tanhf(acc[4][j] + bo), c5 = tanhf(acc[5][j] + bo);
                float c6 = tanhf(acc[6][j] + bo), c7 = tanhf(acc[7][j] + bo);
                float4 v0, v1;
                v0.x = uu0.x * hh0.x + (1.f - uu0.x) * c0;
                v0.y = uu0.y * hh0.y + (1.f - uu0.y) * c1;
                v0.z = uu0.z * hh0.z + (1.f - uu0.z) * c2;
                v0.w = uu0.w * hh0.w + (1.f - uu0.w) * c3;
                v1.x = uu1.x * hh1.x + (1.f - uu1.x) * c4;
                v1.y = uu1.y * hh1.y + (1.f - uu1.y) * c5;
                v1.z = uu1.z * hh1.z + (1.f - uu1.z) * c6;
                v1.w = uu1.w * hh1.w + (1.f - uu1.w) * c7;
                *reinterpret_cast<float4*>(&h_new[base]) = v0;
                *reinterpret_cast<float4*>(&h_new[base + 4]) = v1;
                if (outp) {
                    float wf = Wfc[o];
                    outacc[0] += v0.x * wf; outacc[1] += v0.y * wf;
                    outacc[2] += v0.z * wf; outacc[3] += v0.w * wf;
                    outacc[4] += v1.x * wf; outacc[5] += v1.y * wf;
                    outacc[6] += v1.z * wf; outacc[7] += v1.w * wf;
                }
            }
        }
        if (outp) {
#pragma unroll
            for (int i = 0; i < 8; i++) red[tc][tr * 8 + i] = outacc[i];
            __syncthreads();
            if (tid < 64) {
                float s = bfc[0];
#pragma unroll
                for (int q = 0; q < 16; q++) s += red[q][tid];
                outp[(long)tid * NN + n] = s;
            }
        }
    }
}

// ---------------- host orchestration -----------------------------------------
static inline void smm_launch(const float* S,
                              const float* X0, const float* X1, long xz,
                              const float* Z0, const float* Z1, long zz,
                              float* Y0, float* Y1, long yz,
                              int J, float alpha, float beta, int nz) {
    dim3 grid((J + 127) / 128, (NN + 63) / 64, nz);
    smm_kernel<<<grid, 128>>>(S, X0, X1, xz, Z0, Z1, zz, Y0, Y1, yz, J, alpha, beta);
}

extern "C" void kernel_launch(void* const* d_in, const int* in_sizes, int n_in,
                              void* d_out, int out_size) {
    const float* inputs = (const float*)d_in[0];
    const float* init_state = (const float*)d_in[1];
    const float* adj = (const float*)d_in[2];
    const float* Wg0 = (const float*)d_in[3];
    const float* bg0 = (const float*)d_in[4];
    const float* Wc0 = (const float*)d_in[5];
    const float* bc0 = (const float*)d_in[6];
    const float* Wg1 = (const float*)d_in[7];
    const float* bg1 = (const float*)d_in[8];
    const float* Wc1 = (const float*)d_in[9];
    const float* bc1 = (const float*)d_in[10];
    const float* Wfc = (const float*)d_in[11];
    const float* bfc = (const float*)d_in[12];
    float* out = (float*)d_out;

    void* p;
    cudaGetSymbolAddress(&p, g_S);      float* S = (float*)p;
    cudaGetSymbolAddress(&p, g_rs);     float* rs = (float*)p;
    cudaGetSymbolAddress(&p, g_cs);     float* cs = (float*)p;
    cudaGetSymbolAddress(&p, g_xx);     float* xx = (float*)p;
    cudaGetSymbolAddress(&p, g_xxcheb); float* xxcheb = (float*)p;
    cudaGetSymbolAddress(&p, g_x1cheb); float* x1cheb = (float*)p;
    cudaGetSymbolAddress(&p, g_hcheb);  float* hcheb = (float*)p;
    cudaGetSymbolAddress(&p, g_h0a);    float* h0a = (float*)p;
    cudaGetSymbolAddress(&p, g_h0b);    float* h0b = (float*)p;
    cudaGetSymbolAddress(&p, g_h1a);    float* h1a = (float*)p;
    cudaGetSymbolAddress(&p, g_h1b);    float* h1b = (float*)p;
    cudaGetSymbolAddress(&p, g_u);      float* u = (float*)p;
    cudaGetSymbolAddress(&p, g_rh);     float* rh = (float*)p;

    const long hs = (long)NN * HH * BB;
    const long xs0 = (long)NN * BB;
    const int nelem = NN * HH * BB;

    sums_kernel<<<(NN + 255) / 256, 256>>>(adj, rs, cs);
    build_S_kernel<<<(NN * NN + 255) / 256, 256>>>(adj, rs, cs, S);

    pack_state_kernel<<<(nelem + 255) / 256, 256>>>(init_state, h0a);
    pack_state_kernel<<<(nelem + 255) / 256, 256>>>(init_state + (long)BB * NN * HH, h1a);

    zero_kernel<<<(BB * NN + 255) / 256, 256>>>(out, BB * NN);

    for (int t = 0; t < 12; t++) {
        float* h0_old = (t & 1) ? h0b : h0a;
        float* h0_new = (t & 1) ? h0a : h0b;
        float* h1_old = (t & 1) ? h1b : h1a;
        float* h1_new = (t & 1) ? h1a : h1b;

        // ---- layer 0 ----
        pack_x_kernel<<<(NN * BB + 255) / 256, 256>>>(inputs + (long)t * BB * NN, xx);

        // x-part cheb (J=64), shared by gate+candidate
        smm_launch(S, xx, 0, 0, 0, 0, 0, xxcheb, 0, 2 * xs0, BB, 1.f, 0.f, 2);
        smm_launch(S, xxcheb, 0, 2 * xs0, xx, 0, 0, xxcheb + xs0, 0, 2 * xs0, BB, 2.f, -1.f, 2);

        // gate0: h cheb on h0_old
        smm_launch(S, h0_old, 0, 0, 0, 0, 0, hcheb, 0, 2 * hs, HH * BB, 1.f, 0.f, 2);
        smm_launch(S, hcheb, 0, 2 * hs, h0_old, 0, 0, hcheb + hs, 0, 2 * hs, HH * BB, 2.f, -1.f, 2);
        dense_kernel<<<NN, 128>>>(xx, xxcheb, 1, h0_old, hcheb, Wg0, bg0, 2 * HH, 325, 0,
                                  rh, u, 0, h0_old, 0, 0, 0, 0);

        // cand0: h cheb on r*h
        smm_launch(S, rh, 0, 0, 0, 0, 0, hcheb, 0, 2 * hs, HH * BB, 1.f, 0.f, 2);
        smm_launch(S, hcheb, 0, 2 * hs, rh, 0, 0, hcheb + hs, 0, 2 * hs, HH * BB, 2.f, -1.f, 2);
        dense_kernel<<<NN, 128>>>(xx, xxcheb, 1, rh, hcheb, Wc0, bc0, HH, 325, 1,
                                  0, 0, u, h0_old, h0_new, 0, 0, 0);

        // ---- layer 1: fused x1cheb (on h0_new) + gate1 cheb (on h1_old), z=4 ----
        smm_launch(S, h0_new, h1_old, 0, 0, 0, 0, x1cheb, hcheb, 2 * hs, HH * BB, 1.f, 0.f, 4);
        smm_launch(S, x1cheb, hcheb, 2 * hs, h0_new, h1_old, 0,
                   x1cheb + hs, hcheb + hs, 2 * hs, HH * BB, 2.f, -1.f, 4);
        dense_kernel<<<NN, 128>>>(h0_new, x1cheb, HH, h1_old, hcheb, Wg1, bg1, 2 * HH, 640, 0,
                                  rh, u, 0, h1_old, 0, 0, 0, 0);

        // cand1
        smm_launch(S, rh, 0, 0, 0, 0, 0, hcheb, 0, 2 * hs, HH * BB, 1.f, 0.f, 2);
        smm_launch(S, hcheb, 0, 2 * hs, rh, 0, 0, hcheb + hs, 0, 2 * hs, HH * BB, 2.f, -1.f, 2);
        dense_kernel<<<NN, 128>>>(h0_new, x1cheb, HH, rh, hcheb, Wc1, bc1, HH, 640, 1,
                                  0, 0, u, h1_old, h1_new, Wfc, bfc,
                                  out + (long)(t + 1) * BB * NN);
    }
}